// round 1
// baseline (speedup 1.0000x reference)
#include <cuda_runtime.h>
#include <cstddef>

// Problem constants (fixed by reference: B=128, C=512, H=W=32)
#define BB   128
#define CC   512
#define SS   1024            // H*W
#define PER  (CC * SS)       // elements per sample = 524288

#define BM 128
#define BN 128
#define BK 16

// Scratch (device globals: allocation-free per harness rules)
__device__ float g_mu[BB];
__device__ float g_rs[BB];
__device__ float g_hdn[(size_t)BB * SS * CC];   // 256 MB intermediate (B, S, C) row-major

// ---------------------------------------------------------------------------
// Kernel 1: per-sample mean / rsqrt(var+eps)
// ---------------------------------------------------------------------------
__inline__ __device__ float warp_sum(float v) {
    #pragma unroll
    for (int o = 16; o > 0; o >>= 1) v += __shfl_down_sync(0xffffffffu, v, o);
    return v;
}

__global__ __launch_bounds__(1024) void ln_stats_kernel(const float* __restrict__ x) {
    const int b = blockIdx.x;
    const float4* xb = reinterpret_cast<const float4*>(x + (size_t)b * PER);
    float s = 0.f, q = 0.f;
    for (int i = threadIdx.x; i < PER / 4; i += 1024) {
        float4 v = xb[i];
        s += (v.x + v.y) + (v.z + v.w);
        q += (v.x * v.x + v.y * v.y) + (v.z * v.z + v.w * v.w);
    }
    __shared__ float sh_s[32], sh_q[32];
    const int lane = threadIdx.x & 31, warp = threadIdx.x >> 5;
    s = warp_sum(s); q = warp_sum(q);
    if (lane == 0) { sh_s[warp] = s; sh_q[warp] = q; }
    __syncthreads();
    if (warp == 0) {
        s = sh_s[lane]; q = sh_q[lane];
        s = warp_sum(s); q = warp_sum(q);
        if (lane == 0) {
            float mu = s / (float)PER;
            float var = q / (float)PER - mu * mu;
            g_mu[b] = mu;
            g_rs[b] = rsqrtf(var + 1e-5f);
        }
    }
}

// ---------------------------------------------------------------------------
// Kernel 2: fused LN-normalize + GEMM1 + bias + ReLU
//   hdn[b,s,d] = relu( b1[d] + sum_c A[b,s,c] * w1[d,c] )
//   A[b,s,c]   = (x[b,c,s]-mu_b)*rs_b*ln_w[c,s] + ln_b[c,s]
// Thread map: tx(0..15) -> n (fast, so hdn stores along C are coalesced),
//             ty(0..15) -> m
// ---------------------------------------------------------------------------
__global__ __launch_bounds__(256) void gemm1_kernel(
    const float* __restrict__ x,
    const float* __restrict__ lnw,
    const float* __restrict__ lnb,
    const float* __restrict__ w1,
    const float* __restrict__ b1)
{
    __shared__ float As[BK][BM];
    __shared__ float Bs[BK][BN];

    const int nb = blockIdx.x;            // 0..3
    const int mb = blockIdx.y;            // 0..1023
    const int b  = mb >> 3;
    const int s0 = (mb & 7) << 7;
    const int n0 = nb << 7;

    const float mu = g_mu[b];
    const float rs = g_rs[b];

    const int t  = threadIdx.x;
    const int tx = t & 15;                // -> n
    const int ty = t >> 4;                // -> m

    float acc[8][8];
    #pragma unroll
    for (int i = 0; i < 8; i++)
        #pragma unroll
        for (int j = 0; j < 8; j++) acc[i][j] = 0.f;

    const float* xb = x + (size_t)b * PER + s0;   // x[b, c, s0 + m]

    for (int c0 = 0; c0 < CC; c0 += BK) {
        // A tile: 16 x 128 normalized elements, coalesced along m
        #pragma unroll
        for (int r = 0; r < 8; r++) {
            int idx = t + r * 256;
            int k = idx >> 7, m = idx & 127;
            int c = c0 + k;
            float v  = xb[c * SS + m];
            float w  = lnw[c * SS + s0 + m];
            float be = lnb[c * SS + s0 + m];
            As[k][m] = (v - mu) * rs * w + be;
        }
        // B tile: w1 rows, float4 along k (coalesced)
        #pragma unroll
        for (int r = 0; r < 2; r++) {
            int f = t + r * 256;
            int n = f >> 2, k4 = (f & 3) << 2;
            float4 v = *reinterpret_cast<const float4*>(&w1[(size_t)(n0 + n) * CC + c0 + k4]);
            Bs[k4 + 0][n] = v.x; Bs[k4 + 1][n] = v.y;
            Bs[k4 + 2][n] = v.z; Bs[k4 + 3][n] = v.w;
        }
        __syncthreads();
        #pragma unroll
        for (int k = 0; k < BK; k++) {
            float ra[8], rb[8];
            *reinterpret_cast<float4*>(&ra[0]) = *reinterpret_cast<float4*>(&As[k][ty * 8]);
            *reinterpret_cast<float4*>(&ra[4]) = *reinterpret_cast<float4*>(&As[k][ty * 8 + 4]);
            *reinterpret_cast<float4*>(&rb[0]) = *reinterpret_cast<float4*>(&Bs[k][tx * 8]);
            *reinterpret_cast<float4*>(&rb[4]) = *reinterpret_cast<float4*>(&Bs[k][tx * 8 + 4]);
            #pragma unroll
            for (int i = 0; i < 8; i++)
                #pragma unroll
                for (int j = 0; j < 8; j++)
                    acc[i][j] = fmaf(ra[i], rb[j], acc[i][j]);
        }
        __syncthreads();
    }

    float bias[8];
    *reinterpret_cast<float4*>(&bias[0]) = *reinterpret_cast<const float4*>(&b1[n0 + tx * 8]);
    *reinterpret_cast<float4*>(&bias[4]) = *reinterpret_cast<const float4*>(&b1[n0 + tx * 8 + 4]);

    float* outp = g_hdn + ((size_t)(b * SS + s0)) * CC + n0;
    #pragma unroll
    for (int i = 0; i < 8; i++) {
        int m = ty * 8 + i;
        float4 o0, o1;
        o0.x = fmaxf(acc[i][0] + bias[0], 0.f);
        o0.y = fmaxf(acc[i][1] + bias[1], 0.f);
        o0.z = fmaxf(acc[i][2] + bias[2], 0.f);
        o0.w = fmaxf(acc[i][3] + bias[3], 0.f);
        o1.x = fmaxf(acc[i][4] + bias[4], 0.f);
        o1.y = fmaxf(acc[i][5] + bias[5], 0.f);
        o1.z = fmaxf(acc[i][6] + bias[6], 0.f);
        o1.w = fmaxf(acc[i][7] + bias[7], 0.f);
        *reinterpret_cast<float4*>(&outp[(size_t)m * CC + tx * 8])     = o0;
        *reinterpret_cast<float4*>(&outp[(size_t)m * CC + tx * 8 + 4]) = o1;
    }
}

// ---------------------------------------------------------------------------
// Kernel 3: GEMM2 + bias + transposed store
//   out[b,e,s] = b2[e] + sum_d hdn[b,s,d] * w2[e,d]
// Thread map: tx(0..15) -> m (fast, so stores along s are coalesced),
//             ty(0..15) -> n
// ---------------------------------------------------------------------------
__global__ __launch_bounds__(256) void gemm2_kernel(
    const float* __restrict__ w2,
    const float* __restrict__ b2,
    float* __restrict__ out)
{
    __shared__ float As[BK][BM];
    __shared__ float Bs[BK][BN];

    const int nb = blockIdx.x;
    const int mb = blockIdx.y;
    const int b  = mb >> 3;
    const int s0 = (mb & 7) << 7;
    const int n0 = nb << 7;

    const int t  = threadIdx.x;
    const int tx = t & 15;                // -> m
    const int ty = t >> 4;                // -> n

    float acc[8][8];                      // acc[j (n)][i (m)]
    #pragma unroll
    for (int j = 0; j < 8; j++)
        #pragma unroll
        for (int i = 0; i < 8; i++) acc[j][i] = 0.f;

    const float* hdn = g_hdn + ((size_t)(b * SS + s0)) * CC;

    for (int c0 = 0; c0 < CC; c0 += BK) {
        // A tile from hdn: float4 along k (coalesced)
        #pragma unroll
        for (int r = 0; r < 2; r++) {
            int f = t + r * 256;
            int m = f >> 2, k4 = (f & 3) << 2;
            float4 v = *reinterpret_cast<const float4*>(&hdn[(size_t)m * CC + c0 + k4]);
            As[k4 + 0][m] = v.x; As[k4 + 1][m] = v.y;
            As[k4 + 2][m] = v.z; As[k4 + 3][m] = v.w;
        }
        // B tile from w2
        #pragma unroll
        for (int r = 0; r < 2; r++) {
            int f = t + r * 256;
            int n = f >> 2, k4 = (f & 3) << 2;
            float4 v = *reinterpret_cast<const float4*>(&w2[(size_t)(n0 + n) * CC + c0 + k4]);
            Bs[k4 + 0][n] = v.x; Bs[k4 + 1][n] = v.y;
            Bs[k4 + 2][n] = v.z; Bs[k4 + 3][n] = v.w;
        }
        __syncthreads();
        #pragma unroll
        for (int k = 0; k < BK; k++) {
            float rm[8], rn[8];
            *reinterpret_cast<float4*>(&rm[0]) = *reinterpret_cast<float4*>(&As[k][tx * 8]);
            *reinterpret_cast<float4*>(&rm[4]) = *reinterpret_cast<float4*>(&As[k][tx * 8 + 4]);
            *reinterpret_cast<float4*>(&rn[0]) = *reinterpret_cast<float4*>(&Bs[k][ty * 8]);
            *reinterpret_cast<float4*>(&rn[4]) = *reinterpret_cast<float4*>(&Bs[k][ty * 8 + 4]);
            #pragma unroll
            for (int j = 0; j < 8; j++)
                #pragma unroll
                for (int i = 0; i < 8; i++)
                    acc[j][i] = fmaf(rn[j], rm[i], acc[j][i]);
        }
        __syncthreads();
    }

    // Transposed store: out[b, e, s], coalesced along s (tx fast)
    #pragma unroll
    for (int j = 0; j < 8; j++) {
        int e = n0 + ty * 8 + j;
        float bias = b2[e];
        float* row = out + (size_t)b * PER + (size_t)e * SS + s0 + tx * 8;
        float4 o0, o1;
        o0.x = acc[j][0] + bias; o0.y = acc[j][1] + bias;
        o0.z = acc[j][2] + bias; o0.w = acc[j][3] + bias;
        o1.x = acc[j][4] + bias; o1.y = acc[j][5] + bias;
        o1.z = acc[j][6] + bias; o1.w = acc[j][7] + bias;
        *reinterpret_cast<float4*>(&row[0]) = o0;
        *reinterpret_cast<float4*>(&row[4]) = o1;
    }
}

// ---------------------------------------------------------------------------
extern "C" void kernel_launch(void* const* d_in, const int* in_sizes, int n_in,
                              void* d_out, int out_size)
{
    const float* x   = (const float*)d_in[0];
    const float* lnw = (const float*)d_in[1];
    const float* lnb = (const float*)d_in[2];
    const float* w1  = (const float*)d_in[3];
    const float* b1  = (const float*)d_in[4];
    const float* w2  = (const float*)d_in[5];
    const float* b2  = (const float*)d_in[6];
    float* out = (float*)d_out;

    ln_stats_kernel<<<BB, 1024>>>(x);

    dim3 grid(CC / BN, BB * SS / BM);   // (4, 1024)
    gemm1_kernel<<<grid, 256>>>(x, lnw, lnb, w1, b1);
    gemm2_kernel<<<grid, 256>>>(w2, b2, out);
}

// round 4
// speedup vs baseline: 2.5906x; 2.5906x over previous
#include <cuda_runtime.h>
#include <cuda_bf16.h>
#include <cstdint>
#include <cstddef>

// Problem constants: B=128, C=512, H=W=32
#define BB   128
#define CC   512
#define SSZ  1024
#define PER  (CC * SSZ)
#define MTOT (BB * SSZ)          // 131072 tokens

// ---------------------------------------------------------------------------
// Scratch (device globals; allocation-free per harness rules)
// ---------------------------------------------------------------------------
__device__ float g_mu[BB];
__device__ float g_rs[BB];
__device__ __nv_bfloat16 g_Ahi[(size_t)MTOT * CC];
__device__ __nv_bfloat16 g_Alo[(size_t)MTOT * CC];
__device__ __nv_bfloat16 g_Hhi[(size_t)MTOT * CC];
__device__ __nv_bfloat16 g_Hlo[(size_t)MTOT * CC];
__device__ __nv_bfloat16 g_W1hi[CC * CC];
__device__ __nv_bfloat16 g_W1lo[CC * CC];
__device__ __nv_bfloat16 g_W2hi[CC * CC];
__device__ __nv_bfloat16 g_W2lo[CC * CC];

// ---------------------------------------------------------------------------
// PTX helpers (all portable >= sm_80; no tcgen05 — unavailable at sm_103 target)
// ---------------------------------------------------------------------------
__device__ __forceinline__ uint32_t smem_u32(const void* p) {
    uint32_t a;
    asm("{ .reg .u64 t; cvta.to.shared.u64 t, %1; cvt.u32.u64 %0, t; }" : "=r"(a) : "l"(p));
    return a;
}
#define CP_ASYNC16(saddr, gptr) \
    asm volatile("cp.async.cg.shared.global [%0], [%1], 16;" :: "r"(saddr), "l"(gptr) : "memory")
#define CP_COMMIT() asm volatile("cp.async.commit_group;" ::: "memory")
#define CP_WAIT1()  asm volatile("cp.async.wait_group 1;" ::: "memory")
#define CP_WAIT0()  asm volatile("cp.async.wait_group 0;" ::: "memory")

__device__ __forceinline__ void ldsm_x4(uint32_t* r, uint32_t addr) {
    asm volatile("ldmatrix.sync.aligned.m8n8.x4.shared.b16 {%0,%1,%2,%3}, [%4];"
        : "=r"(r[0]), "=r"(r[1]), "=r"(r[2]), "=r"(r[3]) : "r"(addr));
}
__device__ __forceinline__ void mma_bf16(float* d, const uint32_t* a, const uint32_t* b) {
    asm volatile("mma.sync.aligned.m16n8k16.row.col.f32.bf16.bf16.f32 "
        "{%0,%1,%2,%3}, {%4,%5,%6,%7}, {%8,%9}, {%0,%1,%2,%3};"
        : "+f"(d[0]), "+f"(d[1]), "+f"(d[2]), "+f"(d[3])
        : "r"(a[0]), "r"(a[1]), "r"(a[2]), "r"(a[3]), "r"(b[0]), "r"(b[1]));
}

#define SWZ(off) ((off) ^ (((off) >> 3) & 0x70))

__device__ __forceinline__ uint32_t pack_bf2(__nv_bfloat16 a, __nv_bfloat16 b) {
    return (uint32_t)__bfloat16_as_ushort(a) | ((uint32_t)__bfloat16_as_ushort(b) << 16);
}

// ---------------------------------------------------------------------------
// Kernel 1: per-sample LN stats
// ---------------------------------------------------------------------------
__inline__ __device__ float warp_sum(float v) {
    #pragma unroll
    for (int o = 16; o > 0; o >>= 1) v += __shfl_down_sync(0xffffffffu, v, o);
    return v;
}
__global__ __launch_bounds__(1024) void ln_stats_kernel(const float* __restrict__ x) {
    const int b = blockIdx.x;
    const float4* xb = reinterpret_cast<const float4*>(x + (size_t)b * PER);
    float s = 0.f, q = 0.f;
    for (int i = threadIdx.x; i < PER / 4; i += 1024) {
        float4 v = xb[i];
        s += (v.x + v.y) + (v.z + v.w);
        q += (v.x * v.x + v.y * v.y) + (v.z * v.z + v.w * v.w);
    }
    __shared__ float sh_s[32], sh_q[32];
    const int lane = threadIdx.x & 31, warp = threadIdx.x >> 5;
    s = warp_sum(s); q = warp_sum(q);
    if (lane == 0) { sh_s[warp] = s; sh_q[warp] = q; }
    __syncthreads();
    if (warp == 0) {
        s = sh_s[lane]; q = sh_q[lane];
        s = warp_sum(s); q = warp_sum(q);
        if (lane == 0) {
            float mu = s / (float)PER;
            float var = q / (float)PER - mu * mu;
            g_mu[b] = mu;
            g_rs[b] = rsqrtf(var + 1e-5f);
        }
    }
}

// ---------------------------------------------------------------------------
// Kernel 2: weight split fp32 -> bf16 hi/lo
// ---------------------------------------------------------------------------
__global__ __launch_bounds__(256) void wsplit_kernel(const float* __restrict__ w, int which) {
    int i = blockIdx.x * 256 + threadIdx.x;
    float v = w[i];
    __nv_bfloat16 h = __float2bfloat16(v);
    __nv_bfloat16 l = __float2bfloat16(v - __bfloat162float(h));
    if (which == 0) { g_W1hi[i] = h; g_W1lo[i] = l; }
    else            { g_W2hi[i] = h; g_W2lo[i] = l; }
}

// ---------------------------------------------------------------------------
// Kernel 3: LN-normalize + transpose to token-major + split to bf16 hi/lo
// ---------------------------------------------------------------------------
__global__ __launch_bounds__(256) void lnconv_kernel(
    const float* __restrict__ x, const float* __restrict__ lnw, const float* __restrict__ lnb)
{
    __shared__ float t[32][33];
    const int b  = blockIdx.z;
    const int c0 = blockIdx.y * 32;
    const int s0 = blockIdx.x * 32;
    const float mu = g_mu[b], rs = g_rs[b];
    const int tx = threadIdx.x, ty = threadIdx.y;   // 32 x 8

    #pragma unroll
    for (int r = 0; r < 4; r++) {
        int cl = ty + r * 8;
        int c = c0 + cl, s = s0 + tx;
        float v = x[(size_t)b * PER + c * SSZ + s];
        t[cl][tx] = (v - mu) * rs * lnw[c * SSZ + s] + lnb[c * SSZ + s];
    }
    __syncthreads();
    const size_t rowbase = (size_t)(b * SSZ + s0);
    #pragma unroll
    for (int r = 0; r < 4; r++) {
        int sl = ty + r * 8;
        float a = t[tx][sl];
        __nv_bfloat16 h = __float2bfloat16(a);
        size_t o = (rowbase + sl) * CC + c0 + tx;
        g_Ahi[o] = h;
        g_Alo[o] = __float2bfloat16(a - __bfloat162float(h));
    }
}

// ---------------------------------------------------------------------------
// GEMM via mma.sync bf16 split (3 terms), 128x128x64 tiles, cp.async 2-stage.
//   EPI=0: H = relu(A * W1^T + b1) -> split bf16 (g_Hhi/g_Hlo)
//   EPI=1: out[b,e,s] = H * W2^T + b2, transposed store via smem
// Warp layout: 8 warps = 2 (m) x 4 (n); warp tile 64x32.
// Stage layout (bytes): Ahi @0, Alo @16384, Bhi @32768, Blo @49152; 64KB/stage.
// ---------------------------------------------------------------------------
#define STAGE_BYTES 65536
#define SMEM_TOTAL  131072

template <int EPI>
__global__ __launch_bounds__(256) void gemm_mma_kernel(
    const float* __restrict__ bias, float* __restrict__ out)
{
    extern __shared__ char smem[];
    const uint32_t sb = smem_u32(smem);
    const int tid = threadIdx.x, wid = tid >> 5, lane = tid & 31;
    const int m0 = blockIdx.y * 128;
    const int n0 = blockIdx.x * 128;
    const int wm = wid & 1, wn = wid >> 1;

    const __nv_bfloat16* Ahi = (EPI == 0) ? g_Ahi : g_Hhi;
    const __nv_bfloat16* Alo = (EPI == 0) ? g_Alo : g_Hlo;
    const __nv_bfloat16* Bhi = (EPI == 0) ? g_W1hi : g_W2hi;
    const __nv_bfloat16* Blo = (EPI == 0) ? g_W1lo : g_W2lo;

    // ---- per-thread load indices (16B chunks; 128B rows, SW128 swizzle) ----
    const int ld_row = tid >> 3;           // 0..31 (x4 iters -> 128 rows... see loop)
    const int ld_c16 = tid & 7;            // 16B chunk within 128B row

    // ---- ldmatrix lane addressing ----
    // A: row = lane&15 within m16 tile, kbyte = (lane>>4)*16
    const int a_lrow = lane & 15;
    const uint32_t a_lkb = (lane >> 4) * 16;
    // B: row = (lane&7) + ((lane>>4)<<3) within n16 pair, kbyte = ((lane>>3)&1)*16
    const int b_lrow = (lane & 7) + ((lane >> 4) << 3);
    const uint32_t b_lkb = ((lane >> 3) & 1) * 16;

    float acc[4][4][4];
    #pragma unroll
    for (int i = 0; i < 4; i++)
        #pragma unroll
        for (int j = 0; j < 4; j++)
            #pragma unroll
            for (int r = 0; r < 4; r++) acc[i][j][r] = 0.f;

    // ---- stage loader ----
    auto load_stage = [&](int buf, int k0) {
        const uint32_t st = sb + buf * STAGE_BYTES;
        #pragma unroll
        for (int i = 0; i < 4; i++) {
            int row = ld_row + i * 32;
            uint32_t so = SWZ((uint32_t)(row * 128 + ld_c16 * 16));
            size_t ga = (size_t)(m0 + row) * CC + k0 + ld_c16 * 8;
            size_t gb = (size_t)(n0 + row) * CC + k0 + ld_c16 * 8;
            CP_ASYNC16(st + so,         Ahi + ga);
            CP_ASYNC16(st + 16384 + so, Alo + ga);
            CP_ASYNC16(st + 32768 + so, Bhi + gb);
            CP_ASYNC16(st + 49152 + so, Blo + gb);
        }
        CP_COMMIT();
    };

    load_stage(0, 0);

    for (int ci = 0; ci < 8; ci++) {
        if (ci + 1 < 8) load_stage((ci + 1) & 1, (ci + 1) * 64);
        if (ci + 1 < 8) { CP_WAIT1(); } else { CP_WAIT0(); }
        __syncthreads();

        const uint32_t st = sb + (ci & 1) * STAGE_BYTES;

        // Precompute per-mt A row bases and per-p B row bases
        uint32_t aBase[4], aSwz[4], bBase[2], bSwz[2];
        #pragma unroll
        for (int mt = 0; mt < 4; mt++) {
            int row = wm * 64 + mt * 16 + a_lrow;
            aBase[mt] = st + (uint32_t)(row * 128);
            aSwz[mt]  = (uint32_t)((row & 7) * 16);
        }
        #pragma unroll
        for (int p = 0; p < 2; p++) {
            int row = wn * 32 + p * 16 + b_lrow;
            bBase[p] = st + 32768 + (uint32_t)(row * 128);
            bSwz[p]  = (uint32_t)((row & 7) * 16);
        }

        #pragma unroll
        for (int ks = 0; ks < 4; ks++) {
            uint32_t ah[4][4], al[4][4], bh[2][4], bl[2][4];
            #pragma unroll
            for (int mt = 0; mt < 4; mt++) {
                uint32_t ko = ((uint32_t)(ks * 32) + a_lkb) ^ aSwz[mt];
                ldsm_x4(ah[mt], aBase[mt] + ko);
                ldsm_x4(al[mt], aBase[mt] + 16384 + ko);
            }
            #pragma unroll
            for (int p = 0; p < 2; p++) {
                uint32_t ko = ((uint32_t)(ks * 32) + b_lkb) ^ bSwz[p];
                ldsm_x4(bh[p], bBase[p] + ko);
                ldsm_x4(bl[p], bBase[p] + 16384 + ko);
            }
            // term 1: Ahi * Bhi
            #pragma unroll
            for (int mt = 0; mt < 4; mt++)
                #pragma unroll
                for (int nt = 0; nt < 4; nt++)
                    mma_bf16(acc[mt][nt], ah[mt], &bh[nt >> 1][(nt & 1) * 2]);
            // term 2: Ahi * Blo
            #pragma unroll
            for (int mt = 0; mt < 4; mt++)
                #pragma unroll
                for (int nt = 0; nt < 4; nt++)
                    mma_bf16(acc[mt][nt], ah[mt], &bl[nt >> 1][(nt & 1) * 2]);
            // term 3: Alo * Bhi
            #pragma unroll
            for (int mt = 0; mt < 4; mt++)
                #pragma unroll
                for (int nt = 0; nt < 4; nt++)
                    mma_bf16(acc[mt][nt], al[mt], &bh[nt >> 1][(nt & 1) * 2]);
        }
        __syncthreads();
    }

    // ---- epilogue ----
    const int qrow = lane >> 2;             // l/4
    const int qcol = (lane & 3) * 2;        // 2*(l%4)

    if (EPI == 0) {
        #pragma unroll
        for (int mt = 0; mt < 4; mt++) {
            #pragma unroll
            for (int nt = 0; nt < 4; nt++) {
                int n = n0 + wn * 32 + nt * 8 + qcol;
                float bv0 = bias[n], bv1 = bias[n + 1];
                #pragma unroll
                for (int half = 0; half < 2; half++) {
                    int m = m0 + wm * 64 + mt * 16 + qrow + half * 8;
                    float v0 = fmaxf(acc[mt][nt][half * 2 + 0] + bv0, 0.f);
                    float v1 = fmaxf(acc[mt][nt][half * 2 + 1] + bv1, 0.f);
                    __nv_bfloat16 h0 = __float2bfloat16(v0);
                    __nv_bfloat16 h1 = __float2bfloat16(v1);
                    __nv_bfloat16 l0 = __float2bfloat16(v0 - __bfloat162float(h0));
                    __nv_bfloat16 l1 = __float2bfloat16(v1 - __bfloat162float(h1));
                    size_t o = (size_t)m * CC + n;
                    *reinterpret_cast<uint32_t*>(g_Hhi + o) = pack_bf2(h0, h1);
                    *reinterpret_cast<uint32_t*>(g_Hlo + o) = pack_bf2(l0, l1);
                }
            }
        }
    } else {
        // Transpose via smem: sm[e_local][s_local], row stride 132 floats.
        float* sm = reinterpret_cast<float*>(smem);
        #pragma unroll
        for (int mt = 0; mt < 4; mt++) {
            #pragma unroll
            for (int nt = 0; nt < 4; nt++) {
                int e = wn * 32 + nt * 8 + qcol;
                #pragma unroll
                for (int half = 0; half < 2; half++) {
                    int s = wm * 64 + mt * 16 + qrow + half * 8;
                    sm[(e + 0) * 132 + s] = acc[mt][nt][half * 2 + 0];
                    sm[(e + 1) * 132 + s] = acc[mt][nt][half * 2 + 1];
                }
            }
        }
        __syncthreads();
        const int e = tid >> 1;
        const int sh = (tid & 1) * 64;
        const float bv = bias[n0 + e];
        const int b = m0 >> 10;                 // 128 tokens per block, same sample
        const int s_base = (m0 & 1023) + sh;
        float* op = out + (size_t)b * PER + (size_t)(n0 + e) * SSZ + s_base;
        #pragma unroll
        for (int i = 0; i < 16; i++) {
            float4 v = *reinterpret_cast<float4*>(&sm[e * 132 + sh + i * 4]);
            v.x += bv; v.y += bv; v.z += bv; v.w += bv;
            reinterpret_cast<float4*>(op)[i] = v;
        }
    }
}

// ---------------------------------------------------------------------------
extern "C" void kernel_launch(void* const* d_in, const int* in_sizes, int n_in,
                              void* d_out, int out_size)
{
    const float* x   = (const float*)d_in[0];
    const float* lnw = (const float*)d_in[1];
    const float* lnb = (const float*)d_in[2];
    const float* w1  = (const float*)d_in[3];
    const float* b1  = (const float*)d_in[4];
    const float* w2  = (const float*)d_in[5];
    const float* b2  = (const float*)d_in[6];
    float* out = (float*)d_out;

    static int configured = 0;
    cudaFuncSetAttribute(gemm_mma_kernel<0>, cudaFuncAttributeMaxDynamicSharedMemorySize, SMEM_TOTAL);
    cudaFuncSetAttribute(gemm_mma_kernel<1>, cudaFuncAttributeMaxDynamicSharedMemorySize, SMEM_TOTAL);
    (void)configured;

    ln_stats_kernel<<<BB, 1024>>>(x);
    wsplit_kernel<<<CC * CC / 256, 256>>>(w1, 0);
    wsplit_kernel<<<CC * CC / 256, 256>>>(w2, 1);
    lnconv_kernel<<<dim3(SSZ / 32, CC / 32, BB), dim3(32, 8)>>>(x, lnw, lnb);

    dim3 grid(CC / 128, MTOT / 128);      // (4, 1024)
    gemm_mma_kernel<0><<<grid, 256, SMEM_TOTAL>>>(b1, nullptr);
    gemm_mma_kernel<1><<<grid, 256, SMEM_TOTAL>>>(b2, out);
}